// round 14
// baseline (speedup 1.0000x reference)
#include <cuda_runtime.h>
#include <cuda_bf16.h>
#include <math.h>
#include <stdint.h>

#define B_ 8
#define N_ 256
#define F_ 59
#define C_ 128
#define G_ 8            // receivers per main block
#define TILE 64         // rows per tile
#define MAXROWS 512
#define LOG2E 1.4426950408889634f
#define AS 136          // bf16 elems per padded row (A and W tiles), K=128
#define KSTEPS 8
#define SCS 132         // f32 elems per padded score row

// ---------------- device scratch ----------------
__device__ float  g_asrc[B_*N_*C_];      // raw a_src (x @ W_src^T)
__device__ float  g_pj[B_*N_*C_];        // P[node][d] = <posn6, pw'_d>
__device__ float2 g_vp[B_*N_*C_];        // interleaved {v, P[node][d]}
__device__ float  g_tdst[B_*N_*C_];      // log2e-folded w'.a_dst + b'
__device__ float  g_pbf[C_];             // folded pos bias pb'
__device__ __nv_bfloat16 g_awhi[C_*C_];  // folded attn_w*log2e, [d][c], hi
__device__ __nv_bfloat16 g_awlo[C_*C_];  // lo residual

// ---------------- smem byte offsets (main kernel), 115392 B ----------------
#define OFF_WHI   0          // weights hi bf16 [128][AS] = 34816
#define OFF_WLO   34816      //                              34816 (end 69632)
#define OFF_AHI   69632      // A hi bf16 [64][AS]           17408
#define OFF_ALO   87040      // A lo                         17408 (end 104448)
#define OFF_SC    69632      // f32 e [64][SCS] = 33792 (ALIAS of A region)
#define OFF_GI    104448     // [8][128] f32 = 4096   Gi = pb' + P[i]
#define OFF_TD    108544     // [8][128] f32 = 4096
#define OFF_GEO   112640     // [8][3] f32 = 96 -> 128
#define OFF_ROWS  112768     // int[512] = 2048
#define OFF_MASK  114816     // int[64] = 256
#define OFF_WOFF  115072     // int[64] = 256
#define OFF_ROFF  115328     // int[9] -> 64
#define SMEM_MAIN 115392

static __device__ __forceinline__ uint32_t smem_u32(const void* p) {
    uint32_t a;
    asm("{ .reg .u64 t; cvta.to.shared.u64 t, %1; cvt.u32.u64 %0, t; }" : "=r"(a) : "l"(p));
    return a;
}

#define LDM4(r, addr) \
    asm volatile("ldmatrix.sync.aligned.m8n8.x4.shared.b16 {%0,%1,%2,%3}, [%4];" \
        : "=r"((r)[0]), "=r"((r)[1]), "=r"((r)[2]), "=r"((r)[3]) : "r"(addr))

#define MMA_BF16(c, a, b0, b1) \
    asm volatile("mma.sync.aligned.m16n8k16.row.col.f32.bf16.bf16.f32 " \
        "{%0,%1,%2,%3}, {%4,%5,%6,%7}, {%8,%9}, {%0,%1,%2,%3};" \
        : "+f"((c)[0]), "+f"((c)[1]), "+f"((c)[2]), "+f"((c)[3]) \
        : "r"((a)[0]), "r"((a)[1]), "r"((a)[2]), "r"((a)[3]), "r"(b0), "r"(b1))

// =====================================================================
// Kernel 1: per-node precompute. grid = 128 (16 nodes), block = 512.
// =====================================================================
__global__ void __launch_bounds__(512, 1)
precompute_kernel(const float* __restrict__ x,
                  const float* __restrict__ pos, const float* __restrict__ nrm,
                  const float* __restrict__ Wl,
                  const float* __restrict__ Ws,
                  const float* __restrict__ Wd,
                  const float* __restrict__ pos_w, const float* __restrict__ pos_b,
                  const float* __restrict__ pg, const float* __restrict__ pb,
                  const float* __restrict__ pm, const float* __restrict__ pv,
                  const float* __restrict__ attn_w, const float* __restrict__ attn_b,
                  const float* __restrict__ ag, const float* __restrict__ ab,
                  const float* __restrict__ am, const float* __restrict__ av)
{
    extern __shared__ float sh[];
    float* s_wl  = sh;                  // [128][60]
    float* s_ws  = s_wl + 128*60;
    float* s_wd  = s_ws + 128*60;
    float* s_aw  = s_wd + 128*60;       // [128][132] folded (x log2e)
    float* s_x   = s_aw + 128*132;      // [16][64]
    float* s_ad  = s_x  + 16*64;        // [16][128]
    float* s_s2  = s_ad + 16*128;       // [128]
    float* s_b2  = s_s2 + 128;          // [128]
    float* s_pw1 = s_b2 + 128;          // [128][6] folded pos weights
    float* s_p6  = s_pw1 + 128*6;       // [16][6] node geometry

    const int t   = threadIdx.x;
    const int blk = blockIdx.x;        // node base = blk*16

    if (t < 128) {
        float s2 = ag[t] * rsqrtf(av[t] + 1e-5f);
        s_b2[t] = (attn_b[t] * s2 + ab[t] - am[t] * s2) * LOG2E;
        s_s2[t] = s2 * LOG2E;
        float s1 = pg[t] * rsqrtf(pv[t] + 1e-5f);
#pragma unroll
        for (int k = 0; k < 6; k++) s_pw1[t*6 + k] = pos_w[t*6 + k] * s1;
        float pbf = pos_b[t] * s1 + pb[t] - pm[t] * s1;
        if (blk == 0) g_pbf[t] = pbf;
    }
    if (t >= 128 && t < 128 + 96) {
        int e = t - 128, n = e / 6, k = e % 6;
        int node = blk*16 + n;
        s_p6[e] = (k < 3) ? pos[node*3 + k] : nrm[node*3 + (k - 3)];
    }
    __syncthreads();

    for (int idx = t; idx < 128*F_; idx += 512) {
        int c = idx / F_, f = idx % F_;
        s_wl[c*60 + f] = Wl[idx];
        s_ws[c*60 + f] = Ws[idx];
        s_wd[c*60 + f] = Wd[idx];
    }
    {
        const float4* aw4 = (const float4*)attn_w;
        for (int i4 = t; i4 < C_*C_/4; i4 += 512) {
            float4 w = aw4[i4];
            int c = i4 >> 5, k = (i4 & 31) * 4;
            float s2 = s_s2[c];
            float* dst = s_aw + c*132 + k;
            dst[0] = w.x*s2; dst[1] = w.y*s2; dst[2] = w.z*s2; dst[3] = w.w*s2;
        }
    }
    for (int idx = t; idx < 16*F_; idx += 512) {
        int n = idx / F_, f = idx % F_;
        s_x[n*64 + f] = x[blk*16*F_ + idx];
    }
    __syncthreads();

    if (blk == 0) {
        for (int idx = t; idx < C_*C_; idx += 512) {
            float w = s_aw[(idx >> 7)*132 + (idx & 127)];
            __nv_bfloat16 h = __float2bfloat16(w);
            g_awhi[idx] = h;
            g_awlo[idx] = __float2bfloat16(w - __bfloat162float(h));
        }
    }

    const int c = t & 127, g = t >> 7;   // g in 0..3, nodes g*4..g*4+3

    float accv[4], accs[4], accd[4];
#pragma unroll
    for (int n = 0; n < 4; n++) { accv[n] = 0.f; accs[n] = 0.f; accd[n] = 0.f; }

    for (int f4 = 0; f4 < 56; f4 += 4) {
        float4 wl4 = *(const float4*)(s_wl + c*60 + f4);
        float4 ws4 = *(const float4*)(s_ws + c*60 + f4);
        float4 wd4 = *(const float4*)(s_wd + c*60 + f4);
#pragma unroll
        for (int n = 0; n < 4; n++) {
            float4 x4 = *(const float4*)(s_x + (g*4 + n)*64 + f4);
            accv[n] = fmaf(x4.x, wl4.x, fmaf(x4.y, wl4.y, fmaf(x4.z, wl4.z, fmaf(x4.w, wl4.w, accv[n]))));
            accs[n] = fmaf(x4.x, ws4.x, fmaf(x4.y, ws4.y, fmaf(x4.z, ws4.z, fmaf(x4.w, ws4.w, accs[n]))));
            accd[n] = fmaf(x4.x, wd4.x, fmaf(x4.y, wd4.y, fmaf(x4.z, wd4.z, fmaf(x4.w, wd4.w, accd[n]))));
        }
    }
#pragma unroll
    for (int f = 56; f < F_; f++) {
        float wl = s_wl[c*60 + f], ws = s_ws[c*60 + f], wd = s_wd[c*60 + f];
#pragma unroll
        for (int n = 0; n < 4; n++) {
            float xv = s_x[(g*4 + n)*64 + f];
            accv[n] = fmaf(xv, wl, accv[n]);
            accs[n] = fmaf(xv, ws, accs[n]);
            accd[n] = fmaf(xv, wd, accd[n]);
        }
    }

    // P[node][c] = <posn6, pw'_c>
    float pwl[6];
#pragma unroll
    for (int k = 0; k < 6; k++) pwl[k] = s_pw1[c*6 + k];

#pragma unroll
    for (int n = 0; n < 4; n++) {
        int node = g*4 + n;
        float pjv = 0.f;
#pragma unroll
        for (int k = 0; k < 6; k++) pjv = fmaf(s_p6[node*6 + k], pwl[k], pjv);
        g_asrc[(blk*16 + node)*C_ + c] = accs[n];
        g_pj[(blk*16 + node)*C_ + c]   = pjv;
        g_vp[(blk*16 + node)*C_ + c]   = make_float2(accv[n], pjv);
        s_ad[node*128 + c] = accd[n];
    }
    __syncthreads();

    // GEMM2: tdst
    float td[4];
#pragma unroll
    for (int n = 0; n < 4; n++) td[n] = 0.f;

    for (int k4 = 0; k4 < C_; k4 += 4) {
        float4 aw4 = *(const float4*)(s_aw + c*132 + k4);
#pragma unroll
        for (int n = 0; n < 4; n++) {
            float4 d4 = *(const float4*)(s_ad + (g*4 + n)*128 + k4);
            td[n] = fmaf(d4.x, aw4.x, fmaf(d4.y, aw4.y, fmaf(d4.z, aw4.z, fmaf(d4.w, aw4.w, td[n]))));
        }
    }
    float b2 = s_b2[c];
#pragma unroll
    for (int n = 0; n < 4; n++) {
        int node = g*4 + n;
        g_tdst[(blk*16 + node)*C_ + c] = td[n] + b2;
    }
}

// =====================================================================
// Kernel 2: fused attention. HMMA score GEMM (a_src folded, K=128),
// rank-1 delta, exp2 on fragments. grid = 256 (8 receivers),
// block = 512, smem 115.4 KB -> 2 CTAs/SM (phase-stall overlap).
// =====================================================================
__global__ void __launch_bounds__(512, 2)
main_kernel(const float* __restrict__ pos, const float* __restrict__ rptr,
            float* __restrict__ out)
{
    extern __shared__ char smem[];
    const uint32_t sb = smem_u32(smem);

    float* s_gi   = (float*)(smem + OFF_GI);
    float* s_td   = (float*)(smem + OFF_TD);
    float* s_geo  = (float*)(smem + OFF_GEO);
    float* s_sc   = (float*)(smem + OFF_SC);
    int*   s_rows = (int*)(smem + OFF_ROWS);
    int*   s_mask = (int*)(smem + OFF_MASK);
    int*   s_woff = (int*)(smem + OFF_WOFF);
    int*   s_roff = (int*)(smem + OFF_ROFF);

    const int blk = blockIdx.x;
    const int b  = blk >> 5;
    const int i0 = (blk & 31) * G_;
    const int t  = threadIdx.x;
    const int wd = t >> 5, ln = t & 31;

    // ---- stage weights hi/lo into [d][AS] tiles ----
    {
        const uint4* srh = (const uint4*)g_awhi;
        const uint4* srl = (const uint4*)g_awlo;
        for (int i4 = t; i4 < C_*C_/8; i4 += 512) {
            int e = i4 * 8, dd = e >> 7, c0 = e & 127;
            int off = (dd*AS + c0) * 2;
            *(uint4*)(smem + OFF_WHI + off) = srh[i4];
            *(uint4*)(smem + OFF_WLO + off) = srl[i4];
        }
    }
    for (int idx = t; idx < G_*C_; idx += 512) {
        int ii = idx >> 7, dd = idx & 127;
        s_td[idx] = g_tdst[(b*N_ + i0 + ii)*C_ + dd];
        s_gi[idx] = g_pbf[dd] + g_pj[(b*N_ + i0 + ii)*C_ + dd];
    }
    if (t < G_*3) {
        int ii = t / 3, k = t % 3;
        s_geo[t] = pos[(b*N_ + i0 + ii)*3 + k];
    }
    __syncthreads();

    float rr;
    { int iv = *(const int*)rptr; rr = (iv > 0 && iv < 1000000) ? (float)iv : *rptr; }
    const float r2 = rr * rr;

    // ---- deterministic sorted compaction (threads 0..255 = candidate j) ----
    unsigned predbits = 0;
    if (t < 256) {
        const float* pj = pos + (b*N_ + t)*3;
        float px = pj[0], py = pj[1], pz = pj[2];
#pragma unroll
        for (int ii = 0; ii < G_; ii++) {
            float dx = s_geo[ii*3+0] - px;
            float dy = s_geo[ii*3+1] - py;
            float dz = s_geo[ii*3+2] - pz;
            if (dx*dx + dy*dy + dz*dz <= r2) predbits |= (1u << ii);
        }
#pragma unroll
        for (int ii = 0; ii < G_; ii++) {
            unsigned msk = __ballot_sync(0xFFFFFFFFu, (predbits >> ii) & 1u);
            if (ln == 0) s_mask[ii*8 + wd] = (int)msk;
        }
    }
    __syncthreads();

    if (t < 32) {
        int ii = ln;
        int cnt = 0;
        if (ii < G_)
            for (int w = 0; w < 8; w++) cnt += __popc((unsigned)s_mask[ii*8 + w]);
        int incl = cnt;
#pragma unroll
        for (int off = 1; off < G_; off <<= 1) {
            int v = __shfl_up_sync(0xFFFFFFFFu, incl, off);
            if (ln >= off) incl += v;
        }
        if (ii < G_) {
            int excl = incl - cnt;
            s_roff[ii] = excl < MAXROWS ? excl : MAXROWS;
            int run = excl;
            for (int w = 0; w < 8; w++) {
                s_woff[ii*8 + w] = run;
                run += __popc((unsigned)s_mask[ii*8 + w]);
            }
            if (ii == G_ - 1) s_roff[G_] = run < MAXROWS ? run : MAXROWS;
        }
    }
    __syncthreads();

    if (t < 256) {
#pragma unroll
        for (int ii = 0; ii < G_; ii++) {
            if ((predbits >> ii) & 1u) {
                unsigned msk = (unsigned)s_mask[ii*8 + wd];
                int idx = s_woff[ii*8 + wd] + __popc(msk & ((1u << ln) - 1u));
                if (idx < MAXROWS) s_rows[idx] = t | (ii << 8);
            }
        }
    }
    __syncthreads();
    const int nrows = s_roff[G_];
    const int T = (nrows + TILE - 1) & ~(TILE - 1);
    if (t < T - nrows) s_rows[nrows + t] = 0;   // benign padding
    __syncthreads();

    // ---- roles ----
    const int d = t & 127, q = t >> 7;   // epilogue: channel, receiver-pair group (0..3)
    const int mt = wd & 3;               // MMA: m-tile (rows mt*16..+15)
    const int nb = wd >> 2;              // MMA: n-block (cols nb*32..+31)

    const int lrow = ln & 15;
    const int lkof = (ln >> 4) * 8;
    const uint32_t aHi0 = sb + OFF_AHI + ((mt*16 + lrow)*AS + lkof)*2;
    const uint32_t aLo0 = aHi0 + (OFF_ALO - OFF_AHI);
    const uint32_t bHi0 = sb + OFF_WHI + ((nb*32 + lrow)*AS + lkof)*2;
    const uint32_t bHi1 = bHi0 + 16*AS*2;
    const uint32_t bLo0 = bHi0 + (OFF_WLO - OFF_WHI);
    const uint32_t bLo1 = bHi1 + (OFF_WLO - OFF_WHI);

    const float*  asb = g_asrc + (size_t)(b*N_)*C_;
    const float*  pjb = g_pj   + (size_t)(b*N_)*C_;
    const float2* vpb = g_vp   + (size_t)(b*N_)*C_;

    float l_[2] = {0.f, 0.f}, o_[2] = {0.f, 0.f};

    for (int base = 0; base < T; base += TILE) {
        // --- A fill: (max(0, Gi - Pj) - a_src) bf16 hi/lo ---
        {
            int arow = t & 63, acg = t >> 6;   // 8 col-groups of 16 c
            int ac0 = acg*16;
            int tag = s_rows[base + arow];
            int aj = tag & 255, aii = tag >> 8;
            float as[16], pjv[16], gi[16];
            {
                const float4* ap = (const float4*)(asb + (size_t)aj*C_ + ac0);
                const float4* pp = (const float4*)(pjb + (size_t)aj*C_ + ac0);
                const float4* gp = (const float4*)(s_gi + aii*C_ + ac0);
#pragma unroll
                for (int p = 0; p < 4; p++) {
                    float4 a4 = ap[p], p4 = pp[p], g4 = gp[p];
                    as[4*p]=a4.x; as[4*p+1]=a4.y; as[4*p+2]=a4.z; as[4*p+3]=a4.w;
                    pjv[4*p]=p4.x; pjv[4*p+1]=p4.y; pjv[4*p+2]=p4.z; pjv[4*p+3]=p4.w;
                    gi[4*p]=g4.x; gi[4*p+1]=g4.y; gi[4*p+2]=g4.z; gi[4*p+3]=g4.w;
                }
            }
            float dv[16];
#pragma unroll
            for (int cc = 0; cc < 16; cc++)
                dv[cc] = fmaxf(gi[cc] - pjv[cc], 0.f) - as[cc];
            unsigned ph[8], pl[8];
#pragma unroll
            for (int p = 0; p < 8; p++) {
                __nv_bfloat162 h2 = __floats2bfloat162_rn(dv[2*p], dv[2*p+1]);
                float q0 = dv[2*p]   - __bfloat162float(h2.x);
                float q1 = dv[2*p+1] - __bfloat162float(h2.y);
                __nv_bfloat162 l2 = __floats2bfloat162_rn(q0, q1);
                ph[p] = *(unsigned*)&h2;
                pl[p] = *(unsigned*)&l2;
            }
            int off = (arow*AS + ac0)*2;
            *(uint4*)(smem + OFF_AHI + off)      = make_uint4(ph[0], ph[1], ph[2], ph[3]);
            *(uint4*)(smem + OFF_AHI + off + 16) = make_uint4(ph[4], ph[5], ph[6], ph[7]);
            *(uint4*)(smem + OFF_ALO + off)      = make_uint4(pl[0], pl[1], pl[2], pl[3]);
            *(uint4*)(smem + OFF_ALO + off + 16) = make_uint4(pl[4], pl[5], pl[6], pl[7]);
        }
        __syncthreads();

        // --- tensor-core score GEMM: 64 rows x 128 cols, 3-way bf16 split ---
        float acc[4][4];
#pragma unroll
        for (int tn = 0; tn < 4; tn++)
#pragma unroll
            for (int i = 0; i < 4; i++) acc[tn][i] = 0.f;

#pragma unroll
        for (int kk = 0; kk < KSTEPS; kk++) {
            const uint32_t ko = kk * 32;
            uint32_t ah[4], al[4], bh0[4], bh1[4], bl0[4], bl1[4];
            LDM4(ah,  aHi0 + ko);
            LDM4(al,  aLo0 + ko);
            LDM4(bh0, bHi0 + ko);
            LDM4(bh1, bHi1 + ko);
            LDM4(bl0, bLo0 + ko);
            LDM4(bl1, bLo1 + ko);
            MMA_BF16(acc[0], ah, bh0[0], bh0[2]);
            MMA_BF16(acc[1], ah, bh0[1], bh0[3]);
            MMA_BF16(acc[2], ah, bh1[0], bh1[2]);
            MMA_BF16(acc[3], ah, bh1[1], bh1[3]);
            MMA_BF16(acc[0], ah, bl0[0], bl0[2]);
            MMA_BF16(acc[1], ah, bl0[1], bl0[3]);
            MMA_BF16(acc[2], ah, bl1[0], bl1[2]);
            MMA_BF16(acc[3], ah, bl1[1], bl1[3]);
            MMA_BF16(acc[0], al, bh0[0], bh0[2]);
            MMA_BF16(acc[1], al, bh0[1], bh0[3]);
            MMA_BF16(acc[2], al, bh1[0], bh1[2]);
            MMA_BF16(acc[3], al, bh1[1], bh1[3]);
        }
        __syncthreads();   // A reads complete; e-store may overwrite A region

        // --- fragment phase: e = exp2(relu(score + tdst)) -> s_sc ---
        {
            int gid = ln >> 2, tq = ln & 3;
            int row0 = mt*16 + gid;
            int ii0 = s_rows[base + row0] >> 8;
            int ii1 = s_rows[base + row0 + 8] >> 8;
            const float* td0 = s_td + ii0*C_;
            const float* td1 = s_td + ii1*C_;
#pragma unroll
            for (int tn = 0; tn < 4; tn++) {
                int col = nb*32 + tn*8 + tq*2;
                float e0 = exp2f(fmaxf(acc[tn][0] + td0[col],     0.f));
                float e1 = exp2f(fmaxf(acc[tn][1] + td0[col + 1], 0.f));
                float e2 = exp2f(fmaxf(acc[tn][2] + td1[col],     0.f));
                float e3 = exp2f(fmaxf(acc[tn][3] + td1[col + 1], 0.f));
                *(float2*)(s_sc + row0*SCS + col)     = make_float2(e0, e1);
                *(float2*)(s_sc + (row0+8)*SCS + col) = make_float2(e2, e3);
            }
        }
        __syncthreads();

        // --- epilogue: batched vp-gather + rank-1 delta + accumulate ---
#pragma unroll
        for (int s = 0; s < 2; s++) {
            int ii = q*2 + s;
            int lo = s_roff[ii]   - base; if (lo < 0)    lo = 0;
            int hi = s_roff[ii+1] - base; if (hi > TILE) hi = TILE;
            const float Gi = s_gi[ii*C_ + d];
            for (int r0b = lo; r0b < hi; r0b += 8) {
                int cnt = hi - r0b; if (cnt > 8) cnt = 8;
                float2 vp[8];
#pragma unroll
                for (int k = 0; k < 8; k++) {
                    if (k < cnt) {
                        int j = s_rows[base + r0b + k] & 255;
                        vp[k] = vpb[(size_t)j*C_ + d];
                    }
                }
#pragma unroll
                for (int k = 0; k < 8; k++) {
                    if (k < cnt) {
                        int r = r0b + k;
                        float e = s_sc[r*SCS + d];
                        float dvv = fmaxf(Gi - vp[k].y, 0.f);
                        l_[s] += e;
                        o_[s] = fmaf(e, vp[k].x + dvv, o_[s]);
                    }
                }
            }
        }
        __syncthreads();
    }

#pragma unroll
    for (int s = 0; s < 2; s++) {
        int ii = q*2 + s;
        out[(b*N_ + i0 + ii)*C_ + d] = o_[s] / l_[s];   // self-loop => l > 0
    }
}

// ---------------- launch ----------------
extern "C" void kernel_launch(void* const* d_in, const int* in_sizes, int n_in,
                              void* d_out, int out_size)
{
    const float* x      = (const float*)d_in[0];
    const float* pos    = (const float*)d_in[1];
    const float* normal = (const float*)d_in[2];
    const float* W_lin  = (const float*)d_in[3];
    const float* W_src  = (const float*)d_in[4];
    const float* W_dst  = (const float*)d_in[5];
    const float* pos_w  = (const float*)d_in[6];
    const float* pos_b  = (const float*)d_in[7];
    const float* pbn_g  = (const float*)d_in[8];
    const float* pbn_b  = (const float*)d_in[9];
    const float* pbn_m  = (const float*)d_in[10];
    const float* pbn_v  = (const float*)d_in[11];
    const float* attn_w = (const float*)d_in[12];
    const float* attn_b = (const float*)d_in[13];
    const float* abn_g  = (const float*)d_in[14];
    const float* abn_b  = (const float*)d_in[15];
    const float* abn_m  = (const float*)d_in[16];
    const float* abn_v  = (const float*)d_in[17];
    const float* rptr   = (const float*)d_in[18];
    float* out = (float*)d_out;

    const size_t smemB = (size_t)(3*128*60 + 128*132 + 16*64 + 16*128 + 256
                                  + 128*6 + 96) * sizeof(float);

    cudaFuncSetAttribute(precompute_kernel, cudaFuncAttributeMaxDynamicSharedMemorySize, (int)smemB);
    cudaFuncSetAttribute(main_kernel,       cudaFuncAttributeMaxDynamicSharedMemorySize, SMEM_MAIN);
    (void)in_sizes; (void)n_in; (void)out_size;

    precompute_kernel<<<B_*N_/16, 512, smemB>>>(x, pos, normal, W_lin, W_src, W_dst,
                                                pos_w, pos_b, pbn_g, pbn_b, pbn_m, pbn_v,
                                                attn_w, attn_b, abn_g, abn_b, abn_m, abn_v);
    main_kernel<<<B_*N_/G_, 512, SMEM_MAIN>>>(pos, rptr, out);
}

// round 15
// speedup vs baseline: 1.0379x; 1.0379x over previous
#include <cuda_runtime.h>
#include <cuda_fp16.h>
#include <math.h>
#include <stdint.h>

#define B_ 8
#define N_ 256
#define F_ 59
#define C_ 128
#define G_ 8            // receivers per main block
#define TILE 64         // rows per tile
#define MAXROWS 512
#define LOG2E 1.4426950408889634f
#define AS 136          // fp16 elems per padded row (A and W tiles), K=128
#define KSTEPS 8
#define SCS 132         // f32 elems per padded score row

// ---------------- device scratch ----------------
__device__ float  g_asrc[B_*N_*C_];      // raw a_src (x @ W_src^T)
__device__ float  g_pj[B_*N_*C_];        // P[node][d] = <posn6, pw'_d>
__device__ float2 g_vp[B_*N_*C_];        // interleaved {v, P[node][d]}
__device__ float  g_tdst[B_*N_*C_];      // log2e-folded w'.a_dst + b'
__device__ float  g_pbf[C_];             // folded pos bias pb'
__device__ __half g_awhi[C_*C_];         // folded attn_w*log2e, [d][c], fp16 hi
__device__ __half g_awlo[C_*C_];         // fp16 lo residual

// ---------------- smem byte offsets (main kernel), ~114.4 KB ----------------
#define OFF_WHI   0          // weights hi fp16 [128][AS] = 34816
#define OFF_WLO   34816      //                              34816 (end 69632)
#define OFF_A     69632      // A fp16 [64][AS]              17408
#define OFF_SC    69632      // f32 e [64][SCS] = 33792 (ALIASES A + extension, end 103424)
#define OFF_GI    103424     // [8][128] f32 = 4096
#define OFF_TD    107520     // [8][128] f32 = 4096
#define OFF_GEO   111616     // [8][3] f32 -> 128
#define OFF_ROWS  111744     // int[512] = 2048
#define OFF_MASK  113792     // int[64] = 256
#define OFF_WOFF  114048     // int[64] = 256
#define OFF_ROFF  114304     // int[9] -> 64
#define SMEM_MAIN 114368

static __device__ __forceinline__ uint32_t smem_u32(const void* p) {
    uint32_t a;
    asm("{ .reg .u64 t; cvta.to.shared.u64 t, %1; cvt.u32.u64 %0, t; }" : "=r"(a) : "l"(p));
    return a;
}

#define LDM4(r, addr) \
    asm volatile("ldmatrix.sync.aligned.m8n8.x4.shared.b16 {%0,%1,%2,%3}, [%4];" \
        : "=r"((r)[0]), "=r"((r)[1]), "=r"((r)[2]), "=r"((r)[3]) : "r"(addr))

#define MMA_F16(c, a, b0, b1) \
    asm volatile("mma.sync.aligned.m16n8k16.row.col.f32.f16.f16.f32 " \
        "{%0,%1,%2,%3}, {%4,%5,%6,%7}, {%8,%9}, {%0,%1,%2,%3};" \
        : "+f"((c)[0]), "+f"((c)[1]), "+f"((c)[2]), "+f"((c)[3]) \
        : "r"((a)[0]), "r"((a)[1]), "r"((a)[2]), "r"((a)[3]), "r"(b0), "r"(b1))

// =====================================================================
// Kernel 1: per-node precompute. grid = 128 (16 nodes), block = 512.
// =====================================================================
__global__ void __launch_bounds__(512, 1)
precompute_kernel(const float* __restrict__ x,
                  const float* __restrict__ pos, const float* __restrict__ nrm,
                  const float* __restrict__ Wl,
                  const float* __restrict__ Ws,
                  const float* __restrict__ Wd,
                  const float* __restrict__ pos_w, const float* __restrict__ pos_b,
                  const float* __restrict__ pg, const float* __restrict__ pb,
                  const float* __restrict__ pm, const float* __restrict__ pv,
                  const float* __restrict__ attn_w, const float* __restrict__ attn_b,
                  const float* __restrict__ ag, const float* __restrict__ ab,
                  const float* __restrict__ am, const float* __restrict__ av)
{
    extern __shared__ float sh[];
    float* s_wl  = sh;                  // [128][60]
    float* s_ws  = s_wl + 128*60;
    float* s_wd  = s_ws + 128*60;
    float* s_aw  = s_wd + 128*60;       // [128][132] folded (x log2e)
    float* s_x   = s_aw + 128*132;      // [16][64]
    float* s_ad  = s_x  + 16*64;        // [16][128]
    float* s_s2  = s_ad + 16*128;       // [128]
    float* s_b2  = s_s2 + 128;          // [128]
    float* s_pw1 = s_b2 + 128;          // [128][6] folded pos weights
    float* s_p6  = s_pw1 + 128*6;       // [16][6] node geometry

    const int t   = threadIdx.x;
    const int blk = blockIdx.x;        // node base = blk*16

    if (t < 128) {
        float s2 = ag[t] * rsqrtf(av[t] + 1e-5f);
        s_b2[t] = (attn_b[t] * s2 + ab[t] - am[t] * s2) * LOG2E;
        s_s2[t] = s2 * LOG2E;
        float s1 = pg[t] * rsqrtf(pv[t] + 1e-5f);
#pragma unroll
        for (int k = 0; k < 6; k++) s_pw1[t*6 + k] = pos_w[t*6 + k] * s1;
        float pbf = pos_b[t] * s1 + pb[t] - pm[t] * s1;
        if (blk == 0) g_pbf[t] = pbf;
    }
    if (t >= 128 && t < 128 + 96) {
        int e = t - 128, n = e / 6, k = e % 6;
        int node = blk*16 + n;
        s_p6[e] = (k < 3) ? pos[node*3 + k] : nrm[node*3 + (k - 3)];
    }
    __syncthreads();

    for (int idx = t; idx < 128*F_; idx += 512) {
        int c = idx / F_, f = idx % F_;
        s_wl[c*60 + f] = Wl[idx];
        s_ws[c*60 + f] = Ws[idx];
        s_wd[c*60 + f] = Wd[idx];
    }
    {
        const float4* aw4 = (const float4*)attn_w;
        for (int i4 = t; i4 < C_*C_/4; i4 += 512) {
            float4 w = aw4[i4];
            int c = i4 >> 5, k = (i4 & 31) * 4;
            float s2 = s_s2[c];
            float* dst = s_aw + c*132 + k;
            dst[0] = w.x*s2; dst[1] = w.y*s2; dst[2] = w.z*s2; dst[3] = w.w*s2;
        }
    }
    for (int idx = t; idx < 16*F_; idx += 512) {
        int n = idx / F_, f = idx % F_;
        s_x[n*64 + f] = x[blk*16*F_ + idx];
    }
    __syncthreads();

    if (blk == 0) {
        for (int idx = t; idx < C_*C_; idx += 512) {
            float w = s_aw[(idx >> 7)*132 + (idx & 127)];
            __half h = __float2half(w);
            g_awhi[idx] = h;
            g_awlo[idx] = __float2half(w - __half2float(h));
        }
    }

    const int c = t & 127, g = t >> 7;   // g in 0..3, nodes g*4..g*4+3

    float accv[4], accs[4], accd[4];
#pragma unroll
    for (int n = 0; n < 4; n++) { accv[n] = 0.f; accs[n] = 0.f; accd[n] = 0.f; }

    for (int f4 = 0; f4 < 56; f4 += 4) {
        float4 wl4 = *(const float4*)(s_wl + c*60 + f4);
        float4 ws4 = *(const float4*)(s_ws + c*60 + f4);
        float4 wd4 = *(const float4*)(s_wd + c*60 + f4);
#pragma unroll
        for (int n = 0; n < 4; n++) {
            float4 x4 = *(const float4*)(s_x + (g*4 + n)*64 + f4);
            accv[n] = fmaf(x4.x, wl4.x, fmaf(x4.y, wl4.y, fmaf(x4.z, wl4.z, fmaf(x4.w, wl4.w, accv[n]))));
            accs[n] = fmaf(x4.x, ws4.x, fmaf(x4.y, ws4.y, fmaf(x4.z, ws4.z, fmaf(x4.w, ws4.w, accs[n]))));
            accd[n] = fmaf(x4.x, wd4.x, fmaf(x4.y, wd4.y, fmaf(x4.z, wd4.z, fmaf(x4.w, wd4.w, accd[n]))));
        }
    }
#pragma unroll
    for (int f = 56; f < F_; f++) {
        float wl = s_wl[c*60 + f], ws = s_ws[c*60 + f], wd = s_wd[c*60 + f];
#pragma unroll
        for (int n = 0; n < 4; n++) {
            float xv = s_x[(g*4 + n)*64 + f];
            accv[n] = fmaf(xv, wl, accv[n]);
            accs[n] = fmaf(xv, ws, accs[n]);
            accd[n] = fmaf(xv, wd, accd[n]);
        }
    }

    // P[node][c] = <posn6, pw'_c>
    float pwl[6];
#pragma unroll
    for (int k = 0; k < 6; k++) pwl[k] = s_pw1[c*6 + k];

#pragma unroll
    for (int n = 0; n < 4; n++) {
        int node = g*4 + n;
        float pjv = 0.f;
#pragma unroll
        for (int k = 0; k < 6; k++) pjv = fmaf(s_p6[node*6 + k], pwl[k], pjv);
        g_asrc[(blk*16 + node)*C_ + c] = accs[n];
        g_pj[(blk*16 + node)*C_ + c]   = pjv;
        g_vp[(blk*16 + node)*C_ + c]   = make_float2(accv[n], pjv);
        s_ad[node*128 + c] = accd[n];
    }
    __syncthreads();

    // GEMM2: tdst
    float td[4];
#pragma unroll
    for (int n = 0; n < 4; n++) td[n] = 0.f;

    for (int k4 = 0; k4 < C_; k4 += 4) {
        float4 aw4 = *(const float4*)(s_aw + c*132 + k4);
#pragma unroll
        for (int n = 0; n < 4; n++) {
            float4 d4 = *(const float4*)(s_ad + (g*4 + n)*128 + k4);
            td[n] = fmaf(d4.x, aw4.x, fmaf(d4.y, aw4.y, fmaf(d4.z, aw4.z, fmaf(d4.w, aw4.w, td[n]))));
        }
    }
    float b2 = s_b2[c];
#pragma unroll
    for (int n = 0; n < 4; n++) {
        int node = g*4 + n;
        g_tdst[(blk*16 + node)*C_ + c] = td[n] + b2;
    }
}

// =====================================================================
// Kernel 2: fused attention. HMMA fp16 2-term split (A single fp16,
// W hi/lo fp16), rank-1 delta, exp2 on fragments.
// grid = 256 (8 receivers), block = 512, 2 CTAs/SM.
// =====================================================================
__global__ void __launch_bounds__(512, 2)
main_kernel(const float* __restrict__ pos, const float* __restrict__ rptr,
            float* __restrict__ out)
{
    extern __shared__ char smem[];
    const uint32_t sb = smem_u32(smem);

    float* s_gi   = (float*)(smem + OFF_GI);
    float* s_td   = (float*)(smem + OFF_TD);
    float* s_geo  = (float*)(smem + OFF_GEO);
    float* s_sc   = (float*)(smem + OFF_SC);
    int*   s_rows = (int*)(smem + OFF_ROWS);
    int*   s_mask = (int*)(smem + OFF_MASK);
    int*   s_woff = (int*)(smem + OFF_WOFF);
    int*   s_roff = (int*)(smem + OFF_ROFF);

    const int blk = blockIdx.x;
    const int b  = blk >> 5;
    const int i0 = (blk & 31) * G_;
    const int t  = threadIdx.x;
    const int wd = t >> 5, ln = t & 31;

    // ---- stage weights hi/lo into [d][AS] fp16 tiles ----
    {
        const uint4* srh = (const uint4*)g_awhi;
        const uint4* srl = (const uint4*)g_awlo;
        for (int i4 = t; i4 < C_*C_/8; i4 += 512) {
            int e = i4 * 8, dd = e >> 7, c0 = e & 127;
            int off = (dd*AS + c0) * 2;
            *(uint4*)(smem + OFF_WHI + off) = srh[i4];
            *(uint4*)(smem + OFF_WLO + off) = srl[i4];
        }
    }
    for (int idx = t; idx < G_*C_; idx += 512) {
        int ii = idx >> 7, dd = idx & 127;
        s_td[idx] = g_tdst[(b*N_ + i0 + ii)*C_ + dd];
        s_gi[idx] = g_pbf[dd] + g_pj[(b*N_ + i0 + ii)*C_ + dd];
    }
    if (t < G_*3) {
        int ii = t / 3, k = t % 3;
        s_geo[t] = pos[(b*N_ + i0 + ii)*3 + k];
    }
    __syncthreads();

    float rr;
    { int iv = *(const int*)rptr; rr = (iv > 0 && iv < 1000000) ? (float)iv : *rptr; }
    const float r2 = rr * rr;

    // ---- deterministic sorted compaction (threads 0..255 = candidate j) ----
    unsigned predbits = 0;
    if (t < 256) {
        const float* pj = pos + (b*N_ + t)*3;
        float px = pj[0], py = pj[1], pz = pj[2];
#pragma unroll
        for (int ii = 0; ii < G_; ii++) {
            float dx = s_geo[ii*3+0] - px;
            float dy = s_geo[ii*3+1] - py;
            float dz = s_geo[ii*3+2] - pz;
            if (dx*dx + dy*dy + dz*dz <= r2) predbits |= (1u << ii);
        }
#pragma unroll
        for (int ii = 0; ii < G_; ii++) {
            unsigned msk = __ballot_sync(0xFFFFFFFFu, (predbits >> ii) & 1u);
            if (ln == 0) s_mask[ii*8 + wd] = (int)msk;
        }
    }
    __syncthreads();

    if (t < 32) {
        int ii = ln;
        int cnt = 0;
        if (ii < G_)
            for (int w = 0; w < 8; w++) cnt += __popc((unsigned)s_mask[ii*8 + w]);
        int incl = cnt;
#pragma unroll
        for (int off = 1; off < G_; off <<= 1) {
            int v = __shfl_up_sync(0xFFFFFFFFu, incl, off);
            if (ln >= off) incl += v;
        }
        if (ii < G_) {
            int excl = incl - cnt;
            s_roff[ii] = excl < MAXROWS ? excl : MAXROWS;
            int run = excl;
            for (int w = 0; w < 8; w++) {
                s_woff[ii*8 + w] = run;
                run += __popc((unsigned)s_mask[ii*8 + w]);
            }
            if (ii == G_ - 1) s_roff[G_] = run < MAXROWS ? run : MAXROWS;
        }
    }
    __syncthreads();

    if (t < 256) {
#pragma unroll
        for (int ii = 0; ii < G_; ii++) {
            if ((predbits >> ii) & 1u) {
                unsigned msk = (unsigned)s_mask[ii*8 + wd];
                int idx = s_woff[ii*8 + wd] + __popc(msk & ((1u << ln) - 1u));
                if (idx < MAXROWS) s_rows[idx] = t | (ii << 8);
            }
        }
    }
    __syncthreads();
    const int nrows = s_roff[G_];
    const int T = (nrows + TILE - 1) & ~(TILE - 1);
    if (t < T - nrows) s_rows[nrows + t] = 0;   // benign padding
    __syncthreads();

    // ---- roles ----
    const int d = t & 127, q = t >> 7;   // epilogue: channel, receiver-pair group (0..3)
    const int mt = wd & 3;               // MMA: m-tile (rows mt*16..+15)
    const int nb = wd >> 2;              // MMA: n-block (cols nb*32..+31)

    const int lrow = ln & 15;
    const int lkof = (ln >> 4) * 8;
    const uint32_t aB0  = sb + OFF_A   + ((mt*16 + lrow)*AS + lkof)*2;
    const uint32_t bHi0 = sb + OFF_WHI + ((nb*32 + lrow)*AS + lkof)*2;
    const uint32_t bHi1 = bHi0 + 16*AS*2;
    const uint32_t bLo0 = bHi0 + (OFF_WLO - OFF_WHI);
    const uint32_t bLo1 = bHi1 + (OFF_WLO - OFF_WHI);

    const float*  asb = g_asrc + (size_t)(b*N_)*C_;
    const float*  pjb = g_pj   + (size_t)(b*N_)*C_;
    const float2* vpb = g_vp   + (size_t)(b*N_)*C_;

    float l_[2] = {0.f, 0.f}, o_[2] = {0.f, 0.f};

    for (int base = 0; base < T; base += TILE) {
        // --- A fill: fp16(max(0, Gi - Pj) - a_src) ---
        {
            int arow = t & 63, acg = t >> 6;   // 8 col-groups of 16 c
            int ac0 = acg*16;
            int tag = s_rows[base + arow];
            int aj = tag & 255, aii = tag >> 8;
            float as[16], pjv[16], gi[16];
            {
                const float4* ap = (const float4*)(asb + (size_t)aj*C_ + ac0);
                const float4* pp = (const float4*)(pjb + (size_t)aj*C_ + ac0);
                const float4* gp = (const float4*)(s_gi + aii*C_ + ac0);
#pragma unroll
                for (int p = 0; p < 4; p++) {
                    float4 a4 = ap[p], p4 = pp[p], g4 = gp[p];
                    as[4*p]=a4.x; as[4*p+1]=a4.y; as[4*p+2]=a4.z; as[4*p+3]=a4.w;
                    pjv[4*p]=p4.x; pjv[4*p+1]=p4.y; pjv[4*p+2]=p4.z; pjv[4*p+3]=p4.w;
                    gi[4*p]=g4.x; gi[4*p+1]=g4.y; gi[4*p+2]=g4.z; gi[4*p+3]=g4.w;
                }
            }
            unsigned ph[8];
#pragma unroll
            for (int p = 0; p < 8; p++) {
                float d0 = fmaxf(gi[2*p]   - pjv[2*p],   0.f) - as[2*p];
                float d1 = fmaxf(gi[2*p+1] - pjv[2*p+1], 0.f) - as[2*p+1];
                __half2 h2 = __floats2half2_rn(d0, d1);
                ph[p] = *(unsigned*)&h2;
            }
            int off = (arow*AS + ac0)*2;
            *(uint4*)(smem + OFF_A + off)      = make_uint4(ph[0], ph[1], ph[2], ph[3]);
            *(uint4*)(smem + OFF_A + off + 16) = make_uint4(ph[4], ph[5], ph[6], ph[7]);
        }
        __syncthreads();

        // --- tensor-core score GEMM: 64x128, fp16 2-term split ---
        float acc[4][4];
#pragma unroll
        for (int tn = 0; tn < 4; tn++)
#pragma unroll
            for (int i = 0; i < 4; i++) acc[tn][i] = 0.f;

#pragma unroll
        for (int kk = 0; kk < KSTEPS; kk++) {
            const uint32_t ko = kk * 32;
            uint32_t a_[4], bh0[4], bh1[4], bl0[4], bl1[4];
            LDM4(a_,  aB0  + ko);
            LDM4(bh0, bHi0 + ko);
            LDM4(bh1, bHi1 + ko);
            LDM4(bl0, bLo0 + ko);
            LDM4(bl1, bLo1 + ko);
            MMA_F16(acc[0], a_, bh0[0], bh0[2]);
            MMA_F16(acc[1], a_, bh0[1], bh0[3]);
            MMA_F16(acc[2], a_, bh1[0], bh1[2]);
            MMA_F16(acc[3], a_, bh1[1], bh1[3]);
            MMA_F16(acc[0], a_, bl0[0], bl0[2]);
            MMA_F16(acc[1], a_, bl0[1], bl0[3]);
            MMA_F16(acc[2], a_, bl1[0], bl1[2]);
            MMA_F16(acc[3], a_, bl1[1], bl1[3]);
        }
        __syncthreads();   // A reads complete; e-store may overwrite A region

        // --- fragment phase: e = exp2(relu(score + tdst)) -> s_sc ---
        {
            int gid = ln >> 2, tq = ln & 3;
            int row0 = mt*16 + gid;
            int ii0 = s_rows[base + row0] >> 8;
            int ii1 = s_rows[base + row0 + 8] >> 8;
            const float* td0 = s_td + ii0*C_;
            const float* td1 = s_td + ii1*C_;
#pragma unroll
            for (int tn = 0; tn < 4; tn++) {
                int col = nb*32 + tn*8 + tq*2;
                float e0 = exp2f(fmaxf(acc[tn][0] + td0[col],     0.f));
                float e1 = exp2f(fmaxf(acc[tn][1] + td0[col + 1], 0.f));
                float e2 = exp2f(fmaxf(acc[tn][2] + td1[col],     0.f));
                float e3 = exp2f(fmaxf(acc[tn][3] + td1[col + 1], 0.f));
                *(float2*)(s_sc + row0*SCS + col)     = make_float2(e0, e1);
                *(float2*)(s_sc + (row0+8)*SCS + col) = make_float2(e2, e3);
            }
        }
        __syncthreads();

        // --- epilogue: batched vp-gather + rank-1 delta + accumulate ---
#pragma unroll
        for (int s = 0; s < 2; s++) {
            int ii = q*2 + s;
            int lo = s_roff[ii]   - base; if (lo < 0)    lo = 0;
            int hi = s_roff[ii+1] - base; if (hi > TILE) hi = TILE;
            const float Gi = s_gi[ii*C_ + d];
            for (int r0b = lo; r0b < hi; r0b += 8) {
                int cnt = hi - r0b; if (cnt > 8) cnt = 8;
                float2 vp[8];
#pragma unroll
                for (int k = 0; k < 8; k++) {
                    if (k < cnt) {
                        int j = s_rows[base + r0b + k] & 255;
                        vp[k] = vpb[(size_t)j*C_ + d];
                    }
                }
#pragma unroll
                for (int k = 0; k < 8; k++) {
                    if (k < cnt) {
                        int r = r0b + k;
                        float e = s_sc[r*SCS + d];
                        float dvv = fmaxf(Gi - vp[k].y, 0.f);
                        l_[s] += e;
                        o_[s] = fmaf(e, vp[k].x + dvv, o_[s]);
                    }
                }
            }
        }
        __syncthreads();
    }

#pragma unroll
    for (int s = 0; s < 2; s++) {
        int ii = q*2 + s;
        out[(b*N_ + i0 + ii)*C_ + d] = o_[s] / l_[s];   // self-loop => l > 0
    }
}

// ---------------- launch ----------------
extern "C" void kernel_launch(void* const* d_in, const int* in_sizes, int n_in,
                              void* d_out, int out_size)
{
    const float* x      = (const float*)d_in[0];
    const float* pos    = (const float*)d_in[1];
    const float* normal = (const float*)d_in[2];
    const float* W_lin  = (const float*)d_in[3];
    const float* W_src  = (const float*)d_in[4];
    const float* W_dst  = (const float*)d_in[5];
    const float* pos_w  = (const float*)d_in[6];
    const float* pos_b  = (const float*)d_in[7];
    const float* pbn_g  = (const float*)d_in[8];
    const float* pbn_b  = (const float*)d_in[9];
    const float* pbn_m  = (const float*)d_in[10];
    const float* pbn_v  = (const float*)d_in[11];
    const float* attn_w = (const float*)d_in[12];
    const float* attn_b = (const float*)d_in[13];
    const float* abn_g  = (const float*)d_in[14];
    const float* abn_b  = (const float*)d_in[15];
    const float* abn_m  = (const float*)d_in[16];
    const float* abn_v  = (const float*)d_in[17];
    const float* rptr   = (const float*)d_in[18];
    float* out = (float*)d_out;

    const size_t smemB = (size_t)(3*128*60 + 128*132 + 16*64 + 16*128 + 256
                                  + 128*6 + 96) * sizeof(float);

    cudaFuncSetAttribute(precompute_kernel, cudaFuncAttributeMaxDynamicSharedMemorySize, (int)smemB);
    cudaFuncSetAttribute(main_kernel,       cudaFuncAttributeMaxDynamicSharedMemorySize, SMEM_MAIN);
    (void)in_sizes; (void)n_in; (void)out_size;

    precompute_kernel<<<B_*N_/16, 512, smemB>>>(x, pos, normal, W_lin, W_src, W_dst,
                                                pos_w, pos_b, pbn_g, pbn_b, pbn_m, pbn_v,
                                                attn_w, attn_b, abn_g, abn_b, abn_m, abn_v);
    main_kernel<<<B_*N_/G_, 512, SMEM_MAIN>>>(pos, rptr, out);
}

// round 16
// speedup vs baseline: 1.2084x; 1.1643x over previous
#include <cuda_runtime.h>
#include <cuda_fp16.h>
#include <math.h>
#include <stdint.h>

#define B_ 8
#define N_ 256
#define F_ 59
#define C_ 128
#define G_ 8            // receivers per main block
#define TILE 64         // rows per tile
#define MAXROWS 512
#define LOG2E 1.4426950408889634f
#define AS 136          // fp16 elems per padded row (A and W tiles), K=128
#define KSTEPS 8
#define SCS 132         // f32 elems per padded score row

// ---------------- device scratch ----------------
__device__ float  g_asrc[B_*N_*C_];      // raw a_src (x @ W_src^T)
__device__ float  g_pj[B_*N_*C_];        // P[node][d] = <posn6, pw'_d>
__device__ float2 g_vp[B_*N_*C_];        // interleaved {v, P[node][d]}
__device__ float  g_tdst[B_*N_*C_];      // log2e-folded w'.a_dst + b'
__device__ float  g_pbf[C_];             // folded pos bias pb'
__device__ __half g_aw16[C_*C_];         // folded attn_w*log2e, [d][c], fp16

// ---------------- smem byte offsets (main kernel), 96960 B ----------------
#define OFF_W     0          // weights fp16 [128][AS] = 34816
#define OFF_A     34816      // A fp16 [64][AS] = 17408      (end 52224)
#define OFF_SC    52224      // f32 e [64][SCS] = 33792      (end 86016)
#define OFF_GI    86016      // [8][128] f32 = 4096
#define OFF_TD    90112      // [8][128] f32 = 4096
#define OFF_GEO   94208      // [8][3] f32 -> 128
#define OFF_ROWS  94336      // int[512] = 2048
#define OFF_MASK  96384      // int[64] = 256
#define OFF_WOFF  96640      // int[64] = 256
#define OFF_ROFF  96896      // int[9] -> 64
#define SMEM_MAIN 96960

static __device__ __forceinline__ uint32_t smem_u32(const void* p) {
    uint32_t a;
    asm("{ .reg .u64 t; cvta.to.shared.u64 t, %1; cvt.u32.u64 %0, t; }" : "=r"(a) : "l"(p));
    return a;
}

#define LDM4(r, addr) \
    asm volatile("ldmatrix.sync.aligned.m8n8.x4.shared.b16 {%0,%1,%2,%3}, [%4];" \
        : "=r"((r)[0]), "=r"((r)[1]), "=r"((r)[2]), "=r"((r)[3]) : "r"(addr))

#define MMA_F16(c, a, b0, b1) \
    asm volatile("mma.sync.aligned.m16n8k16.row.col.f32.f16.f16.f32 " \
        "{%0,%1,%2,%3}, {%4,%5,%6,%7}, {%8,%9}, {%0,%1,%2,%3};" \
        : "+f"((c)[0]), "+f"((c)[1]), "+f"((c)[2]), "+f"((c)[3]) \
        : "r"((a)[0]), "r"((a)[1]), "r"((a)[2]), "r"((a)[3]), "r"(b0), "r"(b1))

// =====================================================================
// Kernel 1: per-node precompute. grid = 128 (16 nodes), block = 512.
// =====================================================================
__global__ void __launch_bounds__(512, 1)
precompute_kernel(const float* __restrict__ x,
                  const float* __restrict__ pos, const float* __restrict__ nrm,
                  const float* __restrict__ Wl,
                  const float* __restrict__ Ws,
                  const float* __restrict__ Wd,
                  const float* __restrict__ pos_w, const float* __restrict__ pos_b,
                  const float* __restrict__ pg, const float* __restrict__ pb,
                  const float* __restrict__ pm, const float* __restrict__ pv,
                  const float* __restrict__ attn_w, const float* __restrict__ attn_b,
                  const float* __restrict__ ag, const float* __restrict__ ab,
                  const float* __restrict__ am, const float* __restrict__ av)
{
    extern __shared__ float sh[];
    float* s_wl  = sh;                  // [128][60]
    float* s_ws  = s_wl + 128*60;
    float* s_wd  = s_ws + 128*60;
    float* s_aw  = s_wd + 128*60;       // [128][132] folded (x log2e)
    float* s_x   = s_aw + 128*132;      // [16][64]
    float* s_ad  = s_x  + 16*64;        // [16][128]
    float* s_s2  = s_ad + 16*128;       // [128]
    float* s_b2  = s_s2 + 128;          // [128]
    float* s_pw1 = s_b2 + 128;          // [128][6] folded pos weights
    float* s_p6  = s_pw1 + 128*6;       // [16][6] node geometry

    const int t   = threadIdx.x;
    const int blk = blockIdx.x;        // node base = blk*16

    if (t < 128) {
        float s2 = ag[t] * rsqrtf(av[t] + 1e-5f);
        s_b2[t] = (attn_b[t] * s2 + ab[t] - am[t] * s2) * LOG2E;
        s_s2[t] = s2 * LOG2E;
        float s1 = pg[t] * rsqrtf(pv[t] + 1e-5f);
#pragma unroll
        for (int k = 0; k < 6; k++) s_pw1[t*6 + k] = pos_w[t*6 + k] * s1;
        float pbf = pos_b[t] * s1 + pb[t] - pm[t] * s1;
        if (blk == 0) g_pbf[t] = pbf;
    }
    if (t >= 128 && t < 128 + 96) {
        int e = t - 128, n = e / 6, k = e % 6;
        int node = blk*16 + n;
        s_p6[e] = (k < 3) ? pos[node*3 + k] : nrm[node*3 + (k - 3)];
    }
    __syncthreads();

    for (int idx = t; idx < 128*F_; idx += 512) {
        int c = idx / F_, f = idx % F_;
        s_wl[c*60 + f] = Wl[idx];
        s_ws[c*60 + f] = Ws[idx];
        s_wd[c*60 + f] = Wd[idx];
    }
    {
        const float4* aw4 = (const float4*)attn_w;
        for (int i4 = t; i4 < C_*C_/4; i4 += 512) {
            float4 w = aw4[i4];
            int c = i4 >> 5, k = (i4 & 31) * 4;
            float s2 = s_s2[c];
            float* dst = s_aw + c*132 + k;
            dst[0] = w.x*s2; dst[1] = w.y*s2; dst[2] = w.z*s2; dst[3] = w.w*s2;
        }
    }
    for (int idx = t; idx < 16*F_; idx += 512) {
        int n = idx / F_, f = idx % F_;
        s_x[n*64 + f] = x[blk*16*F_ + idx];
    }
    __syncthreads();

    if (blk == 0) {
        for (int idx = t; idx < C_*C_; idx += 512) {
            float w = s_aw[(idx >> 7)*132 + (idx & 127)];
            g_aw16[idx] = __float2half(w);
        }
    }

    const int c = t & 127, g = t >> 7;   // g in 0..3, nodes g*4..g*4+3

    float accv[4], accs[4], accd[4];
#pragma unroll
    for (int n = 0; n < 4; n++) { accv[n] = 0.f; accs[n] = 0.f; accd[n] = 0.f; }

    for (int f4 = 0; f4 < 56; f4 += 4) {
        float4 wl4 = *(const float4*)(s_wl + c*60 + f4);
        float4 ws4 = *(const float4*)(s_ws + c*60 + f4);
        float4 wd4 = *(const float4*)(s_wd + c*60 + f4);
#pragma unroll
        for (int n = 0; n < 4; n++) {
            float4 x4 = *(const float4*)(s_x + (g*4 + n)*64 + f4);
            accv[n] = fmaf(x4.x, wl4.x, fmaf(x4.y, wl4.y, fmaf(x4.z, wl4.z, fmaf(x4.w, wl4.w, accv[n]))));
            accs[n] = fmaf(x4.x, ws4.x, fmaf(x4.y, ws4.y, fmaf(x4.z, ws4.z, fmaf(x4.w, ws4.w, accs[n]))));
            accd[n] = fmaf(x4.x, wd4.x, fmaf(x4.y, wd4.y, fmaf(x4.z, wd4.z, fmaf(x4.w, wd4.w, accd[n]))));
        }
    }
#pragma unroll
    for (int f = 56; f < F_; f++) {
        float wl = s_wl[c*60 + f], ws = s_ws[c*60 + f], wd = s_wd[c*60 + f];
#pragma unroll
        for (int n = 0; n < 4; n++) {
            float xv = s_x[(g*4 + n)*64 + f];
            accv[n] = fmaf(xv, wl, accv[n]);
            accs[n] = fmaf(xv, ws, accs[n]);
            accd[n] = fmaf(xv, wd, accd[n]);
        }
    }

    // P[node][c] = <posn6, pw'_c>
    float pwl[6];
#pragma unroll
    for (int k = 0; k < 6; k++) pwl[k] = s_pw1[c*6 + k];

#pragma unroll
    for (int n = 0; n < 4; n++) {
        int node = g*4 + n;
        float pjv = 0.f;
#pragma unroll
        for (int k = 0; k < 6; k++) pjv = fmaf(s_p6[node*6 + k], pwl[k], pjv);
        g_asrc[(blk*16 + node)*C_ + c] = accs[n];
        g_pj[(blk*16 + node)*C_ + c]   = pjv;
        g_vp[(blk*16 + node)*C_ + c]   = make_float2(accv[n], pjv);
        s_ad[node*128 + c] = accd[n];
    }
    __syncthreads();

    // GEMM2: tdst
    float td[4];
#pragma unroll
    for (int n = 0; n < 4; n++) td[n] = 0.f;

    for (int k4 = 0; k4 < C_; k4 += 4) {
        float4 aw4 = *(const float4*)(s_aw + c*132 + k4);
#pragma unroll
        for (int n = 0; n < 4; n++) {
            float4 d4 = *(const float4*)(s_ad + (g*4 + n)*128 + k4);
            td[n] = fmaf(d4.x, aw4.x, fmaf(d4.y, aw4.y, fmaf(d4.z, aw4.z, fmaf(d4.w, aw4.w, td[n]))));
        }
    }
    float b2 = s_b2[c];
#pragma unroll
    for (int n = 0; n < 4; n++) {
        int node = g*4 + n;
        g_tdst[(blk*16 + node)*C_ + c] = td[n] + b2;
    }
}

// =====================================================================
// Kernel 2: fused attention. Single-pass fp16 HMMA (A fp16, W fp16),
// rank-1 delta, exp2 on fragments, non-aliased SC (3 barriers/tile).
// grid = 256 (8 receivers), block = 512, smem 97 KB -> 2 CTAs/SM.
// =====================================================================
__global__ void __launch_bounds__(512, 2)
main_kernel(const float* __restrict__ pos, const float* __restrict__ rptr,
            float* __restrict__ out)
{
    extern __shared__ char smem[];
    const uint32_t sb = smem_u32(smem);

    float* s_gi   = (float*)(smem + OFF_GI);
    float* s_td   = (float*)(smem + OFF_TD);
    float* s_geo  = (float*)(smem + OFF_GEO);
    float* s_sc   = (float*)(smem + OFF_SC);
    int*   s_rows = (int*)(smem + OFF_ROWS);
    int*   s_mask = (int*)(smem + OFF_MASK);
    int*   s_woff = (int*)(smem + OFF_WOFF);
    int*   s_roff = (int*)(smem + OFF_ROFF);

    const int blk = blockIdx.x;
    const int b  = blk >> 5;
    const int i0 = (blk & 31) * G_;
    const int t  = threadIdx.x;
    const int wd = t >> 5, ln = t & 31;

    // ---- stage fp16 weights into [d][AS] tile ----
    {
        const uint4* srw = (const uint4*)g_aw16;
        for (int i4 = t; i4 < C_*C_/8; i4 += 512) {
            int e = i4 * 8, dd = e >> 7, c0 = e & 127;
            *(uint4*)(smem + OFF_W + (dd*AS + c0)*2) = srw[i4];
        }
    }
    for (int idx = t; idx < G_*C_; idx += 512) {
        int ii = idx >> 7, dd = idx & 127;
        s_td[idx] = g_tdst[(b*N_ + i0 + ii)*C_ + dd];
        s_gi[idx] = g_pbf[dd] + g_pj[(b*N_ + i0 + ii)*C_ + dd];
    }
    if (t < G_*3) {
        int ii = t / 3, k = t % 3;
        s_geo[t] = pos[(b*N_ + i0 + ii)*3 + k];
    }
    __syncthreads();

    float rr;
    { int iv = *(const int*)rptr; rr = (iv > 0 && iv < 1000000) ? (float)iv : *rptr; }
    const float r2 = rr * rr;

    // ---- deterministic sorted compaction (threads 0..255 = candidate j) ----
    unsigned predbits = 0;
    if (t < 256) {
        const float* pj = pos + (b*N_ + t)*3;
        float px = pj[0], py = pj[1], pz = pj[2];
#pragma unroll
        for (int ii = 0; ii < G_; ii++) {
            float dx = s_geo[ii*3+0] - px;
            float dy = s_geo[ii*3+1] - py;
            float dz = s_geo[ii*3+2] - pz;
            if (dx*dx + dy*dy + dz*dz <= r2) predbits |= (1u << ii);
        }
#pragma unroll
        for (int ii = 0; ii < G_; ii++) {
            unsigned msk = __ballot_sync(0xFFFFFFFFu, (predbits >> ii) & 1u);
            if (ln == 0) s_mask[ii*8 + wd] = (int)msk;
        }
    }
    __syncthreads();

    if (t < 32) {
        int ii = ln;
        int cnt = 0;
        if (ii < G_)
            for (int w = 0; w < 8; w++) cnt += __popc((unsigned)s_mask[ii*8 + w]);
        int incl = cnt;
#pragma unroll
        for (int off = 1; off < G_; off <<= 1) {
            int v = __shfl_up_sync(0xFFFFFFFFu, incl, off);
            if (ln >= off) incl += v;
        }
        if (ii < G_) {
            int excl = incl - cnt;
            s_roff[ii] = excl < MAXROWS ? excl : MAXROWS;
            int run = excl;
            for (int w = 0; w < 8; w++) {
                s_woff[ii*8 + w] = run;
                run += __popc((unsigned)s_mask[ii*8 + w]);
            }
            if (ii == G_ - 1) s_roff[G_] = run < MAXROWS ? run : MAXROWS;
        }
    }
    __syncthreads();

    if (t < 256) {
#pragma unroll
        for (int ii = 0; ii < G_; ii++) {
            if ((predbits >> ii) & 1u) {
                unsigned msk = (unsigned)s_mask[ii*8 + wd];
                int idx = s_woff[ii*8 + wd] + __popc(msk & ((1u << ln) - 1u));
                if (idx < MAXROWS) s_rows[idx] = t | (ii << 8);
            }
        }
    }
    __syncthreads();
    const int nrows = s_roff[G_];
    const int T = (nrows + TILE - 1) & ~(TILE - 1);
    if (t < T - nrows) s_rows[nrows + t] = 0;   // benign padding
    __syncthreads();

    // ---- roles ----
    const int d = t & 127, q = t >> 7;   // epilogue: channel, receiver-pair group (0..3)
    const int mt = wd & 3;               // MMA: m-tile (rows mt*16..+15)
    const int nb = wd >> 2;              // MMA: n-block (cols nb*32..+31)

    const int lrow = ln & 15;
    const int lkof = (ln >> 4) * 8;
    const uint32_t aB0 = sb + OFF_A + ((mt*16 + lrow)*AS + lkof)*2;
    const uint32_t bB0 = sb + OFF_W + ((nb*32 + lrow)*AS + lkof)*2;
    const uint32_t bB1 = bB0 + 16*AS*2;

    const float*  asb = g_asrc + (size_t)(b*N_)*C_;
    const float*  pjb = g_pj   + (size_t)(b*N_)*C_;
    const float2* vpb = g_vp   + (size_t)(b*N_)*C_;

    float l_[2] = {0.f, 0.f}, o_[2] = {0.f, 0.f};

    for (int base = 0; base < T; base += TILE) {
        // --- A fill: fp16(max(0, Gi - Pj) - a_src) ---
        {
            int arow = t & 63, acg = t >> 6;   // 8 col-groups of 16 c
            int ac0 = acg*16;
            int tag = s_rows[base + arow];
            int aj = tag & 255, aii = tag >> 8;
            float as[16], pjv[16], gi[16];
            {
                const float4* ap = (const float4*)(asb + (size_t)aj*C_ + ac0);
                const float4* pp = (const float4*)(pjb + (size_t)aj*C_ + ac0);
                const float4* gp = (const float4*)(s_gi + aii*C_ + ac0);
#pragma unroll
                for (int p = 0; p < 4; p++) {
                    float4 a4 = ap[p], p4 = pp[p], g4 = gp[p];
                    as[4*p]=a4.x; as[4*p+1]=a4.y; as[4*p+2]=a4.z; as[4*p+3]=a4.w;
                    pjv[4*p]=p4.x; pjv[4*p+1]=p4.y; pjv[4*p+2]=p4.z; pjv[4*p+3]=p4.w;
                    gi[4*p]=g4.x; gi[4*p+1]=g4.y; gi[4*p+2]=g4.z; gi[4*p+3]=g4.w;
                }
            }
            unsigned ph[8];
#pragma unroll
            for (int p = 0; p < 8; p++) {
                float d0 = fmaxf(gi[2*p]   - pjv[2*p],   0.f) - as[2*p];
                float d1 = fmaxf(gi[2*p+1] - pjv[2*p+1], 0.f) - as[2*p+1];
                __half2 h2 = __floats2half2_rn(d0, d1);
                ph[p] = *(unsigned*)&h2;
            }
            int off = (arow*AS + ac0)*2;
            *(uint4*)(smem + OFF_A + off)      = make_uint4(ph[0], ph[1], ph[2], ph[3]);
            *(uint4*)(smem + OFF_A + off + 16) = make_uint4(ph[4], ph[5], ph[6], ph[7]);
        }
        __syncthreads();

        // --- tensor-core score GEMM (single fp16 pass) + frag exp2 ---
        float acc[4][4];
#pragma unroll
        for (int tn = 0; tn < 4; tn++)
#pragma unroll
            for (int i = 0; i < 4; i++) acc[tn][i] = 0.f;

#pragma unroll
        for (int kk = 0; kk < KSTEPS; kk++) {
            const uint32_t ko = kk * 32;
            uint32_t a_[4], b0_[4], b1_[4];
            LDM4(a_,  aB0 + ko);
            LDM4(b0_, bB0 + ko);
            LDM4(b1_, bB1 + ko);
            MMA_F16(acc[0], a_, b0_[0], b0_[2]);
            MMA_F16(acc[1], a_, b0_[1], b0_[3]);
            MMA_F16(acc[2], a_, b1_[0], b1_[2]);
            MMA_F16(acc[3], a_, b1_[1], b1_[3]);
        }
        // frag phase: e = exp2(relu(score + tdst)) -> s_sc (own region, no
        // barrier needed after MMA: SC is only read after the next sync)
        {
            int gid = ln >> 2, tq = ln & 3;
            int row0 = mt*16 + gid;
            int ii0 = s_rows[base + row0] >> 8;
            int ii1 = s_rows[base + row0 + 8] >> 8;
            const float* td0 = s_td + ii0*C_;
            const float* td1 = s_td + ii1*C_;
#pragma unroll
            for (int tn = 0; tn < 4; tn++) {
                int col = nb*32 + tn*8 + tq*2;
                float e0 = exp2f(fmaxf(acc[tn][0] + td0[col],     0.f));
                float e1 = exp2f(fmaxf(acc[tn][1] + td0[col + 1], 0.f));
                float e2 = exp2f(fmaxf(acc[tn][2] + td1[col],     0.f));
                float e3 = exp2f(fmaxf(acc[tn][3] + td1[col + 1], 0.f));
                *(float2*)(s_sc + row0*SCS + col)     = make_float2(e0, e1);
                *(float2*)(s_sc + (row0+8)*SCS + col) = make_float2(e2, e3);
            }
        }
        __syncthreads();

        // --- epilogue: batched vp-gather + rank-1 delta + accumulate ---
#pragma unroll
        for (int s = 0; s < 2; s++) {
            int ii = q*2 + s;
            int lo = s_roff[ii]   - base; if (lo < 0)    lo = 0;
            int hi = s_roff[ii+1] - base; if (hi > TILE) hi = TILE;
            const float Gi = s_gi[ii*C_ + d];
            for (int r0b = lo; r0b < hi; r0b += 8) {
                int cnt = hi - r0b; if (cnt > 8) cnt = 8;
                float2 vp[8];
#pragma unroll
                for (int k = 0; k < 8; k++) {
                    if (k < cnt) {
                        int j = s_rows[base + r0b + k] & 255;
                        vp[k] = vpb[(size_t)j*C_ + d];
                    }
                }
#pragma unroll
                for (int k = 0; k < 8; k++) {
                    if (k < cnt) {
                        int r = r0b + k;
                        float e = s_sc[r*SCS + d];
                        float dvv = fmaxf(Gi - vp[k].y, 0.f);
                        l_[s] += e;
                        o_[s] = fmaf(e, vp[k].x + dvv, o_[s]);
                    }
                }
            }
        }
        __syncthreads();
    }

#pragma unroll
    for (int s = 0; s < 2; s++) {
        int ii = q*2 + s;
        out[(b*N_ + i0 + ii)*C_ + d] = o_[s] / l_[s];   // self-loop => l > 0
    }
}

// ---------------- launch ----------------
extern "C" void kernel_launch(void* const* d_in, const int* in_sizes, int n_in,
                              void* d_out, int out_size)
{
    const float* x      = (const float*)d_in[0];
    const float* pos    = (const float*)d_in[1];
    const float* normal = (const float*)d_in[2];
    const float* W_lin  = (const float*)d_in[3];
    const float* W_src  = (const float*)d_in[4];
    const float* W_dst  = (const float*)d_in[5];
    const float* pos_w  = (const float*)d_in[6];
    const float* pos_b  = (const float*)d_in[7];
    const float* pbn_g  = (const float*)d_in[8];
    const float* pbn_b  = (const float*)d_in[9];
    const float* pbn_m  = (const float*)d_in[10];
    const float* pbn_v  = (const float*)d_in[11];
    const float* attn_w = (const float*)d_in[12];
    const float* attn_b = (const float*)d_in[13];
    const float* abn_g  = (const float*)d_in[14];
    const float* abn_b  = (const float*)d_in[15];
    const float* abn_m  = (const float*)d_in[16];
    const float* abn_v  = (const float*)d_in[17];
    const float* rptr   = (const float*)d_in[18];
    float* out = (float*)d_out;

    const size_t smemB = (size_t)(3*128*60 + 128*132 + 16*64 + 16*128 + 256
                                  + 128*6 + 96) * sizeof(float);

    cudaFuncSetAttribute(precompute_kernel, cudaFuncAttributeMaxDynamicSharedMemorySize, (int)smemB);
    cudaFuncSetAttribute(main_kernel,       cudaFuncAttributeMaxDynamicSharedMemorySize, SMEM_MAIN);
    (void)in_sizes; (void)n_in; (void)out_size;

    precompute_kernel<<<B_*N_/16, 512, smemB>>>(x, pos, normal, W_lin, W_src, W_dst,
                                                pos_w, pos_b, pbn_g, pbn_b, pbn_m, pbn_v,
                                                attn_w, attn_b, abn_g, abn_b, abn_m, abn_v);
    main_kernel<<<B_*N_/G_, 512, SMEM_MAIN>>>(pos, rptr, out);
}